// round 14
// baseline (speedup 1.0000x reference)
#include <cuda_runtime.h>
#include <cuda_fp16.h>
#include <stdint.h>

// Problem constants
#define N_GENES 20000
#define N_DRUGS 4000
#define IN_C    1024
#define OUT_C   512
#define N_EDGES 262144
#define MROWS   20096          // padded rows (157 * 128)
#define MB      (MROWS / 16)   // 1256 A row-blocks
#define KB      64             // k16 blocks (1024/16)
#define EB4     (N_EDGES / 1024)  // 256 blocks of 256 thr x 4 edges

// ---------------- device scratch ----------------
__device__ int      g_row_deg[N_GENES];
__device__ int      g_col_deg[N_DRUGS];
__device__ int      g_offs[N_DRUGS];
__device__ int      g_cursor[N_DRUGS];
__device__ int      g_active[N_GENES];
__device__ int      g_rowmap[N_GENES];
__device__ float    g_rowscale[N_GENES];
__device__ int      g_nactive;
__device__ int      g_is64;
__device__ uint32_t g_xf[(size_t)MB * KB * 128];   // A frag plane (fp16x2)
__device__ uint32_t g_wf[64 * KB * 64];            // B frag plane (fp16x2)
__device__ __half   g_xw16[(size_t)MROWS * OUT_C];
__device__ int      g_sidx[N_EDGES];

// ---------------- helpers ----------------
__device__ __forceinline__ uint32_t pack_f16(float f0, float f1) {
    __half2 h = __floats2half2_rn(f0, f1);
    return *(uint32_t*)&h;
}

__device__ __forceinline__ void mma_f16(float* c, const uint32_t* a, const uint32_t* b) {
    asm volatile(
        "mma.sync.aligned.m16n8k16.row.col.f32.f16.f16.f32 "
        "{%0,%1,%2,%3}, {%4,%5,%6,%7}, {%8,%9}, {%0,%1,%2,%3};"
        : "+f"(c[0]), "+f"(c[1]), "+f"(c[2]), "+f"(c[3])
        : "r"(a[0]), "r"(a[1]), "r"(a[2]), "r"(a[3]), "r"(b[0]), "r"(b[1]));
}

// load 4 consecutive edges' (s, d), batched for MLP
__device__ __forceinline__ void load_edge4(const void* ei, int e0, int* s, int* d) {
    if (g_is64) {
        const long long* p = (const long long*)ei;
        long long s0 = p[e0], s1 = p[e0 + 1], s2 = p[e0 + 2], s3 = p[e0 + 3];
        long long d0 = p[N_EDGES + e0], d1 = p[N_EDGES + e0 + 1];
        long long d2 = p[N_EDGES + e0 + 2], d3 = p[N_EDGES + e0 + 3];
        s[0] = (int)s0; s[1] = (int)s1; s[2] = (int)s2; s[3] = (int)s3;
        d[0] = (int)d0; d[1] = (int)d1; d[2] = (int)d2; d[3] = (int)d3;
    } else {
        const int4 sv = *(const int4*)((const int*)ei + e0);
        const int4 dv = *(const int4*)((const int*)ei + N_EDGES + e0);
        s[0] = sv.x; s[1] = sv.y; s[2] = sv.z; s[3] = sv.w;
        d[0] = dv.x; d[1] = dv.y; d[2] = dv.z; d[3] = dv.w;
    }
}

// ---------------- preprocessing ----------------
__global__ __launch_bounds__(256) void k_init(const int* __restrict__ ei32) {
    int i = blockIdx.x * blockDim.x + threadIdx.x;
    const uint4 z = make_uint4(0, 0, 0, 0);
    if (i < 5000) ((uint4*)g_row_deg)[i] = z;
    else if (i < 6000) ((uint4*)g_col_deg)[i - 5000] = z;
    else if (i < 7000) ((uint4*)g_cursor)[i - 6000] = z;
    if (i == 0) g_nactive = 0;
    if (blockIdx.x == 0) {
        __shared__ int any_nonzero;
        if (threadIdx.x == 0) any_nonzero = 0;
        __syncthreads();
        for (int j = threadIdx.x * 2 + 1; j < 8192; j += blockDim.x * 2)
            if (ei32[j] != 0) any_nonzero = 1;
        __syncthreads();
        if (threadIdx.x == 0) g_is64 = any_nonzero ? 0 : 1;
    }
}

// fused: degree x4 (blocks 0..EB4-1) + split_w (blocks EB4..EB4+511)
__global__ __launch_bounds__(256) void k_degree_splitw(const void* __restrict__ ei,
                                                       const float* __restrict__ W) {
    int b = blockIdx.x;
    if (b < EB4) {
        int e0 = (b * 256 + threadIdx.x) * 4;
        int s[4], d[4];
        load_edge4(ei, e0, s, d);
#pragma unroll
        for (int j = 0; j < 4; j++)
            if (s[j] >= 0 && s[j] < N_GENES) atomicAdd(&g_row_deg[s[j]], 1);
#pragma unroll
        for (int j = 0; j < 4; j++)
            if (d[j] >= 0 && d[j] < N_DRUGS) atomicAdd(&g_col_deg[d[j]], 1);
    } else {
        int id = (b - EB4) * 256 + threadIdx.x;
        int lane = id & 31;
        int kb = (id >> 5) & 63;
        int nb = id >> 11;
        int n = nb * 8 + (lane >> 2);
        int kw = kb * 8 + (lane & 3);
        float fa0 = W[(size_t)(2 * kw) * OUT_C + n];
        float fa1 = W[(size_t)(2 * kw + 1) * OUT_C + n];
        float fb0 = W[(size_t)(2 * kw + 8) * OUT_C + n];
        float fb1 = W[(size_t)(2 * kw + 9) * OUT_C + n];
        uint2 h;
        h.x = pack_f16(fa0, fa1);
        h.y = pack_f16(fb0, fb1);
        size_t o = (size_t)(nb * KB + kb) * 32 + lane;
        ((uint2*)g_wf)[o] = h;
    }
}

// compact (blocks 0..19) + warp-shuffle exclusive scan (block 20)
__global__ void k_compact_scan() {
    if (blockIdx.x < 20) {
        int g = blockIdx.x * 1024 + threadIdx.x;
        if (g >= N_GENES) return;
        int deg = g_row_deg[g];
        if (deg > 0) {
            int idx = atomicAdd(&g_nactive, 1);
            g_active[idx] = g;
            g_rowmap[g] = idx;
            g_rowscale[idx] = rsqrtf((float)deg);
        }
    } else {
        __shared__ int warp_excl[32];
        int t = threadIdx.x;
        int lane = t & 31;
        int wid = t >> 5;
        int base = t * 4;
        int v[4];
        int s = 0;
#pragma unroll
        for (int i = 0; i < 4; i++) {
            v[i] = (base + i < N_DRUGS) ? g_col_deg[base + i] : 0;
            s += v[i];
        }
        int inc = s;
#pragma unroll
        for (int d = 1; d < 32; d <<= 1) {
            int x = __shfl_up_sync(0xffffffffu, inc, d);
            if (lane >= d) inc += x;
        }
        if (lane == 31) warp_excl[wid] = inc;
        __syncthreads();
        if (wid == 0) {
            int w = warp_excl[lane];
            int wi = w;
#pragma unroll
            for (int d = 1; d < 32; d <<= 1) {
                int x = __shfl_up_sync(0xffffffffu, wi, d);
                if (lane >= d) wi += x;
            }
            warp_excl[lane] = wi - w;
        }
        __syncthreads();
        int run = (inc - s) + warp_excl[wid];
#pragma unroll
        for (int i = 0; i < 4; i++) {
            if (base + i < N_DRUGS) {
                g_offs[base + i] = run;
                run += v[i];
            }
        }
    }
}

// place, 4 edges per thread for atomic MLP
__global__ __launch_bounds__(256) void k_place(const void* __restrict__ ei) {
    int e0 = (blockIdx.x * 256 + threadIdx.x) * 4;
    int s[4], d[4], p[4];
    load_edge4(ei, e0, s, d);
#pragma unroll
    for (int j = 0; j < 4; j++) {
        bool ok = (s[j] >= 0 && s[j] < N_GENES && d[j] >= 0 && d[j] < N_DRUGS);
        p[j] = ok ? (g_offs[d[j]] + atomicAdd(&g_cursor[d[j]], 1)) : -1;
    }
#pragma unroll
    for (int j = 0; j < 4; j++)
        if (p[j] >= 0) g_sidx[p[j]] = g_rowmap[s[j]];
}

// X active rows -> A frag plane. Two blocks per mb; loads batched for MLP.
__global__ __launch_bounds__(256) void k_split_x(const float* __restrict__ X) {
    const int mb = blockIdx.x >> 1;
    const int half = blockIdx.x & 1;
    const int m0 = mb * 16;
    const int nact = g_nactive;
    if (m0 >= nact) return;
    const int t = threadIdx.x;
    const int lane = t & 31;
    const int w = t >> 5;
    const int g = lane >> 2;
    const int kl = lane & 3;
    const int r0 = m0 + g;
    const int r1 = r0 + 8;
    const float* p0 = (r0 < nact) ? X + (size_t)g_active[r0] * IN_C : 0;
    const float* p1 = (r1 < nact) ? X + (size_t)g_active[r1] * IN_C : 0;
    const float2 z2 = make_float2(0.f, 0.f);

    float2 x0a[4], x0b[4], x1a[4], x1b[4];
#pragma unroll
    for (int i = 0; i < 4; i++) {
        int kb = half * 32 + i * 8 + w;
        int kwA = kb * 8 + kl;
        x0a[i] = p0 ? *(const float2*)(p0 + 2 * kwA) : z2;
        x0b[i] = p0 ? *(const float2*)(p0 + 2 * kwA + 8) : z2;
        x1a[i] = p1 ? *(const float2*)(p1 + 2 * kwA) : z2;
        x1b[i] = p1 ? *(const float2*)(p1 + 2 * kwA + 8) : z2;
    }
#pragma unroll
    for (int i = 0; i < 4; i++) {
        int kb = half * 32 + i * 8 + w;
        uint4 h;
        h.x = pack_f16(x0a[i].x, x0a[i].y);
        h.y = pack_f16(x1a[i].x, x1a[i].y);
        h.z = pack_f16(x0b[i].x, x0b[i].y);
        h.w = pack_f16(x1b[i].x, x1b[i].y);
        size_t o = (size_t)(mb * KB + kb) * 32 + lane;
        ((uint4*)g_xf)[o] = h;
    }
}

// ---------------- zero-staging fp16 GEMM, 4-slot pipeline (PF dist 3) ----------------
__global__ __launch_bounds__(256) void k_gemm(void) {
    const int nact = g_nactive;
    const int m0 = blockIdx.y * 128;
    if (m0 >= nact) return;
    const int n0 = blockIdx.x * 128;

    const int tid = threadIdx.x;
    const int wid = tid >> 5;
    const int lane = tid & 31;
    const int g = lane >> 2;
    const int tig = lane & 3;
    const int mwarp = (wid & 1) * 64;
    const int nwarp = (wid >> 1) * 32;
    const int mb0 = (m0 + mwarp) >> 4;
    const int nb0 = (n0 + nwarp) >> 3;

    const uint4* Af = (const uint4*)g_xf;
    const uint2* Bf = (const uint2*)g_wf;

    float acc[4][4][4];
#pragma unroll
    for (int i = 0; i < 4; i++)
#pragma unroll
        for (int j = 0; j < 4; j++)
#pragma unroll
            for (int r = 0; r < 4; r++) acc[i][j][r] = 0.f;

    uint4 ah[4][4];
    uint2 bh[4][4];

#define LOADK(buf, kb)                                                      \
    do {                                                                    \
        _Pragma("unroll")                                                   \
        for (int mf = 0; mf < 4; mf++) {                                    \
            size_t ai = (size_t)((mb0 + mf) * KB + (kb)) * 32 + lane;       \
            ah[buf][mf] = Af[ai];                                           \
        }                                                                   \
        _Pragma("unroll")                                                   \
        for (int nf = 0; nf < 4; nf++) {                                    \
            size_t bi = (size_t)((nb0 + nf) * KB + (kb)) * 32 + lane;       \
            bh[buf][nf] = Bf[bi];                                           \
        }                                                                   \
    } while (0)

    LOADK(0, 0);
    LOADK(1, 1);
    LOADK(2, 2);
#pragma unroll 4
    for (int kb = 0; kb < KB; kb++) {
        const int cur = kb & 3;
        if (kb + 3 < KB) LOADK((kb + 3) & 3, kb + 3);
#pragma unroll
        for (int mf = 0; mf < 4; mf++) {
#pragma unroll
            for (int nf = 0; nf < 4; nf++) {
                mma_f16(acc[mf][nf], (const uint32_t*)&ah[cur][mf],
                        (const uint32_t*)&bh[cur][nf]);
            }
        }
    }
#undef LOADK

    // epilogue: row scale, fp16 store
#pragma unroll
    for (int mf = 0; mf < 4; mf++) {
        int r0 = m0 + mwarp + mf * 16 + g;
        int r1 = r0 + 8;
#pragma unroll
        for (int nf = 0; nf < 4; nf++) {
            int col = n0 + nwarp + nf * 8 + tig * 2;
            if (r0 < nact) {
                float s0 = g_rowscale[r0];
                __half2 h = __float22half2_rn(
                    make_float2(acc[mf][nf][0] * s0, acc[mf][nf][1] * s0));
                *(__half2*)&g_xw16[(size_t)r0 * OUT_C + col] = h;
            }
            if (r1 < nact) {
                float s1 = g_rowscale[r1];
                __half2 h = __float22half2_rn(
                    make_float2(acc[mf][nf][2] * s1, acc[mf][nf][3] * s1));
                *(__half2*)&g_xw16[(size_t)r1 * OUT_C + col] = h;
            }
        }
    }
}

// ---------------- aggregation (fp16 gather, fp32 accumulate) ----------------
__device__ __forceinline__ void addv(float* acc, uint4 v) {
    const __half2* h = (const __half2*)&v;
#pragma unroll
    for (int j = 0; j < 4; j++) {
        float2 f = __half22float2(h[j]);
        acc[2 * j] += f.x;
        acc[2 * j + 1] += f.y;
    }
}

__global__ __launch_bounds__(64) void k_aggregate(const float* __restrict__ bias,
                                                  float* __restrict__ out) {
    int d = blockIdx.x;
    int t = threadIdx.x;
    int beg = g_offs[d];
    int n = g_col_deg[d];
    int end = beg + n;
    const uint4* xw = (const uint4*)g_xw16;

    float acc[8] = {0.f, 0.f, 0.f, 0.f, 0.f, 0.f, 0.f, 0.f};
    int i = beg;
    for (; i + 3 < end; i += 4) {
        int s0 = g_sidx[i], s1 = g_sidx[i + 1], s2 = g_sidx[i + 2], s3 = g_sidx[i + 3];
        uint4 v0 = xw[(size_t)s0 * 64 + t];
        uint4 v1 = xw[(size_t)s1 * 64 + t];
        uint4 v2 = xw[(size_t)s2 * 64 + t];
        uint4 v3 = xw[(size_t)s3 * 64 + t];
        addv(acc, v0);
        addv(acc, v1);
        addv(acc, v2);
        addv(acc, v3);
    }
    for (; i < end; i++) {
        uint4 v0 = xw[(size_t)g_sidx[i] * 64 + t];
        addv(acc, v0);
    }
    float cs = (n > 0) ? rsqrtf((float)n) : 0.f;
    float4 b0 = ((const float4*)bias)[t * 2];
    float4 b1 = ((const float4*)bias)[t * 2 + 1];
    float4 o0 = make_float4(acc[0] * cs + b0.x, acc[1] * cs + b0.y,
                            acc[2] * cs + b0.z, acc[3] * cs + b0.w);
    float4 o1 = make_float4(acc[4] * cs + b1.x, acc[5] * cs + b1.y,
                            acc[6] * cs + b1.z, acc[7] * cs + b1.w);
    ((float4*)out)[(size_t)d * 128 + t * 2] = o0;
    ((float4*)out)[(size_t)d * 128 + t * 2 + 1] = o1;
}

// ---------------- launch (serial, single stream) ----------------
extern "C" void kernel_launch(void* const* d_in, const int* in_sizes, int n_in,
                              void* d_out, int out_size) {
    const float* x = (const float*)d_in[0];
    const float* w = (const float*)d_in[1];
    const float* bias = (const float*)d_in[2];
    const void* ei = d_in[3];
    float* out = (float*)d_out;

    k_init<<<28, 256>>>((const int*)ei);
    k_degree_splitw<<<EB4 + 512, 256>>>(ei, w);
    k_compact_scan<<<21, 1024>>>();
    k_place<<<EB4, 256>>>(ei);
    k_split_x<<<MB * 2, 256>>>(x);

    dim3 gemm_grid(OUT_C / 128, MROWS / 128);
    k_gemm<<<gemm_grid, 256>>>();

    k_aggregate<<<N_DRUGS, 64>>>(bias, out);
}

// round 15
// speedup vs baseline: 1.1036x; 1.1036x over previous
#include <cuda_runtime.h>
#include <cuda_fp16.h>
#include <stdint.h>

// Problem constants
#define N_GENES 20000
#define N_DRUGS 4000
#define IN_C    1024
#define OUT_C   512
#define N_EDGES 262144
#define MROWS   20096          // padded rows (157 * 128)
#define MB      (MROWS / 16)   // 1256 A row-blocks
#define KB      64             // k16 blocks (1024/16)
#define EBLK    (N_EDGES / 256)

// ---------------- device scratch ----------------
__device__ int      g_row_deg[N_GENES];
__device__ int      g_col_deg[N_DRUGS];
__device__ int      g_offs[N_DRUGS];
__device__ int      g_active[N_GENES];
__device__ int      g_rowmap[N_GENES];
__device__ float    g_rowscale[N_GENES];
__device__ int      g_nactive;
__device__ int      g_is64;
__device__ int      g_rank[N_EDGES];               // per-edge rank within its dst
__device__ uint32_t g_xf[(size_t)MB * KB * 128];   // A frag plane (fp16x2)
__device__ uint32_t g_wf[64 * KB * 64];            // B frag plane (fp16x2)
__device__ __half   g_xw16[(size_t)MROWS * OUT_C];
__device__ int      g_sidx[N_EDGES];

// ---------------- helpers ----------------
__device__ __forceinline__ uint32_t pack_f16(float f0, float f1) {
    __half2 h = __floats2half2_rn(f0, f1);
    return *(uint32_t*)&h;
}

__device__ __forceinline__ void mma_f16(float* c, const uint32_t* a, const uint32_t* b) {
    asm volatile(
        "mma.sync.aligned.m16n8k16.row.col.f32.f16.f16.f32 "
        "{%0,%1,%2,%3}, {%4,%5,%6,%7}, {%8,%9}, {%0,%1,%2,%3};"
        : "+f"(c[0]), "+f"(c[1]), "+f"(c[2]), "+f"(c[3])
        : "r"(a[0]), "r"(a[1]), "r"(a[2]), "r"(a[3]), "r"(b[0]), "r"(b[1]));
}

__device__ __forceinline__ void load_edge(const void* ei, int e, int& s, int& d) {
    if (g_is64) {
        const long long* p = (const long long*)ei;
        s = (int)p[e];
        d = (int)p[N_EDGES + e];
    } else {
        const int* p = (const int*)ei;
        s = p[e];
        d = p[N_EDGES + e];
    }
}

// ---------------- preprocessing ----------------
__global__ __launch_bounds__(256) void k_init(const int* __restrict__ ei32) {
    int i = blockIdx.x * blockDim.x + threadIdx.x;
    const uint4 z = make_uint4(0, 0, 0, 0);
    if (i < 5000) ((uint4*)g_row_deg)[i] = z;
    else if (i < 6000) ((uint4*)g_col_deg)[i - 5000] = z;
    if (i == 0) g_nactive = 0;
    if (blockIdx.x == 0) {
        __shared__ int any_nonzero;
        if (threadIdx.x == 0) any_nonzero = 0;
        __syncthreads();
        for (int j = threadIdx.x * 2 + 1; j < 8192; j += blockDim.x * 2)
            if (ei32[j] != 0) any_nonzero = 1;
        __syncthreads();
        if (threadIdx.x == 0) g_is64 = any_nonzero ? 0 : 1;
    }
}

// fused: degree+rank (blocks 0..EBLK-1) + split_w (blocks EBLK..EBLK+511)
// the col_deg atomic's return value IS the edge's rank within its dst.
__global__ __launch_bounds__(256) void k_degree_splitw(const void* __restrict__ ei,
                                                       const float* __restrict__ W) {
    int b = blockIdx.x;
    if (b < EBLK) {
        int e = b * 256 + threadIdx.x;
        int s, d;
        load_edge(ei, e, s, d);
        if (s >= 0 && s < N_GENES) atomicAdd(&g_row_deg[s], 1);
        if (d >= 0 && d < N_DRUGS) g_rank[e] = atomicAdd(&g_col_deg[d], 1);
    } else {
        int id = (b - EBLK) * 256 + threadIdx.x;
        int lane = id & 31;
        int kb = (id >> 5) & 63;
        int nb = id >> 11;
        int n = nb * 8 + (lane >> 2);
        int kw = kb * 8 + (lane & 3);
        float fa0 = W[(size_t)(2 * kw) * OUT_C + n];
        float fa1 = W[(size_t)(2 * kw + 1) * OUT_C + n];
        float fb0 = W[(size_t)(2 * kw + 8) * OUT_C + n];
        float fb1 = W[(size_t)(2 * kw + 9) * OUT_C + n];
        uint2 h;
        h.x = pack_f16(fa0, fa1);
        h.y = pack_f16(fb0, fb1);
        size_t o = (size_t)(nb * KB + kb) * 32 + lane;
        ((uint2*)g_wf)[o] = h;
    }
}

// compact (blocks 0..19) + warp-shuffle exclusive scan (block 20)
__global__ void k_compact_scan() {
    if (blockIdx.x < 20) {
        int g = blockIdx.x * 1024 + threadIdx.x;
        if (g >= N_GENES) return;
        int deg = g_row_deg[g];
        if (deg > 0) {
            int idx = atomicAdd(&g_nactive, 1);
            g_active[idx] = g;
            g_rowmap[g] = idx;
            g_rowscale[idx] = rsqrtf((float)deg);
        }
    } else {
        __shared__ int warp_excl[32];
        int t = threadIdx.x;
        int lane = t & 31;
        int wid = t >> 5;
        int base = t * 4;
        int v[4];
        int s = 0;
#pragma unroll
        for (int i = 0; i < 4; i++) {
            v[i] = (base + i < N_DRUGS) ? g_col_deg[base + i] : 0;
            s += v[i];
        }
        int inc = s;
#pragma unroll
        for (int d = 1; d < 32; d <<= 1) {
            int x = __shfl_up_sync(0xffffffffu, inc, d);
            if (lane >= d) inc += x;
        }
        if (lane == 31) warp_excl[wid] = inc;
        __syncthreads();
        if (wid == 0) {
            int w = warp_excl[lane];
            int wi = w;
#pragma unroll
            for (int d = 1; d < 32; d <<= 1) {
                int x = __shfl_up_sync(0xffffffffu, wi, d);
                if (lane >= d) wi += x;
            }
            warp_excl[lane] = wi - w;
        }
        __syncthreads();
        int run = (inc - s) + warp_excl[wid];
#pragma unroll
        for (int i = 0; i < 4; i++) {
            if (base + i < N_DRUGS) {
                g_offs[base + i] = run;
                run += v[i];
            }
        }
    }
}

// place: atomic-free scatter using precomputed ranks
__global__ __launch_bounds__(256) void k_place(const void* __restrict__ ei) {
    int e = blockIdx.x * blockDim.x + threadIdx.x;
    if (e >= N_EDGES) return;
    int s, d;
    load_edge(ei, e, s, d);
    if (s < 0 || s >= N_GENES || d < 0 || d >= N_DRUGS) return;
    g_sidx[g_offs[d] + g_rank[e]] = g_rowmap[s];
}

// X active rows -> A frag plane. Two blocks per mb; loads batched for MLP.
__global__ __launch_bounds__(256) void k_split_x(const float* __restrict__ X) {
    const int mb = blockIdx.x >> 1;
    const int half = blockIdx.x & 1;
    const int m0 = mb * 16;
    const int nact = g_nactive;
    if (m0 >= nact) return;
    const int t = threadIdx.x;
    const int lane = t & 31;
    const int w = t >> 5;
    const int g = lane >> 2;
    const int kl = lane & 3;
    const int r0 = m0 + g;
    const int r1 = r0 + 8;
    const float* p0 = (r0 < nact) ? X + (size_t)g_active[r0] * IN_C : 0;
    const float* p1 = (r1 < nact) ? X + (size_t)g_active[r1] * IN_C : 0;
    const float2 z2 = make_float2(0.f, 0.f);

    float2 x0a[4], x0b[4], x1a[4], x1b[4];
#pragma unroll
    for (int i = 0; i < 4; i++) {
        int kb = half * 32 + i * 8 + w;
        int kwA = kb * 8 + kl;
        x0a[i] = p0 ? *(const float2*)(p0 + 2 * kwA) : z2;
        x0b[i] = p0 ? *(const float2*)(p0 + 2 * kwA + 8) : z2;
        x1a[i] = p1 ? *(const float2*)(p1 + 2 * kwA) : z2;
        x1b[i] = p1 ? *(const float2*)(p1 + 2 * kwA + 8) : z2;
    }
#pragma unroll
    for (int i = 0; i < 4; i++) {
        int kb = half * 32 + i * 8 + w;
        uint4 h;
        h.x = pack_f16(x0a[i].x, x0a[i].y);
        h.y = pack_f16(x1a[i].x, x1a[i].y);
        h.z = pack_f16(x0b[i].x, x0b[i].y);
        h.w = pack_f16(x1b[i].x, x1b[i].y);
        size_t o = (size_t)(mb * KB + kb) * 32 + lane;
        ((uint4*)g_xf)[o] = h;
    }
}

// ---------------- zero-staging fp16 GEMM, 4-slot pipeline (PF dist 3) ----------------
__global__ __launch_bounds__(256) void k_gemm(void) {
    const int nact = g_nactive;
    const int m0 = blockIdx.y * 128;
    if (m0 >= nact) return;
    const int n0 = blockIdx.x * 128;

    const int tid = threadIdx.x;
    const int wid = tid >> 5;
    const int lane = tid & 31;
    const int g = lane >> 2;
    const int tig = lane & 3;
    const int mwarp = (wid & 1) * 64;
    const int nwarp = (wid >> 1) * 32;
    const int mb0 = (m0 + mwarp) >> 4;
    const int nb0 = (n0 + nwarp) >> 3;

    const uint4* Af = (const uint4*)g_xf;
    const uint2* Bf = (const uint2*)g_wf;

    float acc[4][4][4];
#pragma unroll
    for (int i = 0; i < 4; i++)
#pragma unroll
        for (int j = 0; j < 4; j++)
#pragma unroll
            for (int r = 0; r < 4; r++) acc[i][j][r] = 0.f;

    uint4 ah[4][4];
    uint2 bh[4][4];

#define LOADK(buf, kb)                                                      \
    do {                                                                    \
        _Pragma("unroll")                                                   \
        for (int mf = 0; mf < 4; mf++) {                                    \
            size_t ai = (size_t)((mb0 + mf) * KB + (kb)) * 32 + lane;       \
            ah[buf][mf] = Af[ai];                                           \
        }                                                                   \
        _Pragma("unroll")                                                   \
        for (int nf = 0; nf < 4; nf++) {                                    \
            size_t bi = (size_t)((nb0 + nf) * KB + (kb)) * 32 + lane;       \
            bh[buf][nf] = Bf[bi];                                           \
        }                                                                   \
    } while (0)

    LOADK(0, 0);
    LOADK(1, 1);
    LOADK(2, 2);
#pragma unroll 4
    for (int kb = 0; kb < KB; kb++) {
        const int cur = kb & 3;
        if (kb + 3 < KB) LOADK((kb + 3) & 3, kb + 3);
#pragma unroll
        for (int mf = 0; mf < 4; mf++) {
#pragma unroll
            for (int nf = 0; nf < 4; nf++) {
                mma_f16(acc[mf][nf], (const uint32_t*)&ah[cur][mf],
                        (const uint32_t*)&bh[cur][nf]);
            }
        }
    }
#undef LOADK

    // epilogue: row scale, fp16 store
#pragma unroll
    for (int mf = 0; mf < 4; mf++) {
        int r0 = m0 + mwarp + mf * 16 + g;
        int r1 = r0 + 8;
#pragma unroll
        for (int nf = 0; nf < 4; nf++) {
            int col = n0 + nwarp + nf * 8 + tig * 2;
            if (r0 < nact) {
                float s0 = g_rowscale[r0];
                __half2 h = __float22half2_rn(
                    make_float2(acc[mf][nf][0] * s0, acc[mf][nf][1] * s0));
                *(__half2*)&g_xw16[(size_t)r0 * OUT_C + col] = h;
            }
            if (r1 < nact) {
                float s1 = g_rowscale[r1];
                __half2 h = __float22half2_rn(
                    make_float2(acc[mf][nf][2] * s1, acc[mf][nf][3] * s1));
                *(__half2*)&g_xw16[(size_t)r1 * OUT_C + col] = h;
            }
        }
    }
}

// ---------------- aggregation (fp16 gather, fp32 accumulate) ----------------
__device__ __forceinline__ void addv(float* acc, uint4 v) {
    const __half2* h = (const __half2*)&v;
#pragma unroll
    for (int j = 0; j < 4; j++) {
        float2 f = __half22float2(h[j]);
        acc[2 * j] += f.x;
        acc[2 * j + 1] += f.y;
    }
}

__global__ __launch_bounds__(64) void k_aggregate(const float* __restrict__ bias,
                                                  float* __restrict__ out) {
    int d = blockIdx.x;
    int t = threadIdx.x;
    int beg = g_offs[d];
    int n = g_col_deg[d];
    int end = beg + n;
    const uint4* xw = (const uint4*)g_xw16;

    float acc[8] = {0.f, 0.f, 0.f, 0.f, 0.f, 0.f, 0.f, 0.f};
    int i = beg;
    for (; i + 3 < end; i += 4) {
        int s0 = g_sidx[i], s1 = g_sidx[i + 1], s2 = g_sidx[i + 2], s3 = g_sidx[i + 3];
        uint4 v0 = xw[(size_t)s0 * 64 + t];
        uint4 v1 = xw[(size_t)s1 * 64 + t];
        uint4 v2 = xw[(size_t)s2 * 64 + t];
        uint4 v3 = xw[(size_t)s3 * 64 + t];
        addv(acc, v0);
        addv(acc, v1);
        addv(acc, v2);
        addv(acc, v3);
    }
    for (; i < end; i++) {
        uint4 v0 = xw[(size_t)g_sidx[i] * 64 + t];
        addv(acc, v0);
    }
    float cs = (n > 0) ? rsqrtf((float)n) : 0.f;
    float4 b0 = ((const float4*)bias)[t * 2];
    float4 b1 = ((const float4*)bias)[t * 2 + 1];
    float4 o0 = make_float4(acc[0] * cs + b0.x, acc[1] * cs + b0.y,
                            acc[2] * cs + b0.z, acc[3] * cs + b0.w);
    float4 o1 = make_float4(acc[4] * cs + b1.x, acc[5] * cs + b1.y,
                            acc[6] * cs + b1.z, acc[7] * cs + b1.w);
    ((float4*)out)[(size_t)d * 128 + t * 2] = o0;
    ((float4*)out)[(size_t)d * 128 + t * 2 + 1] = o1;
}

// ---------------- launch (serial, single stream) ----------------
extern "C" void kernel_launch(void* const* d_in, const int* in_sizes, int n_in,
                              void* d_out, int out_size) {
    const float* x = (const float*)d_in[0];
    const float* w = (const float*)d_in[1];
    const float* bias = (const float*)d_in[2];
    const void* ei = d_in[3];
    float* out = (float*)d_out;

    k_init<<<24, 256>>>((const int*)ei);
    k_degree_splitw<<<EBLK + 512, 256>>>(ei, w);
    k_compact_scan<<<21, 1024>>>();
    k_place<<<EBLK, 256>>>(ei);
    k_split_x<<<MB * 2, 256>>>(x);

    dim3 gemm_grid(OUT_C / 128, MROWS / 128);
    k_gemm<<<gemm_grid, 256>>>();

    k_aggregate<<<N_DRUGS, 64>>>(bias, out);
}

// round 16
// speedup vs baseline: 1.1341x; 1.0276x over previous
#include <cuda_runtime.h>
#include <cuda_fp16.h>
#include <stdint.h>

// Problem constants
#define N_GENES 20000
#define N_DRUGS 4000
#define IN_C    1024
#define OUT_C   512
#define N_EDGES 262144
#define MROWS   20096          // padded rows (157 * 128)
#define MB      (MROWS / 16)   // 1256 A row-blocks
#define KB      64             // k16 blocks (1024/16)
#define EBLK    (N_EDGES / 256)

// ---------------- device scratch ----------------
__device__ int      g_row_deg[N_GENES];
__device__ int      g_col_deg[N_DRUGS];
__device__ int      g_offs[N_DRUGS];
__device__ int      g_active[N_GENES];
__device__ int      g_rowmap[N_GENES];
__device__ float    g_rowscale[N_GENES];
__device__ int      g_nactive;
__device__ int      g_is64;
__device__ int      g_rank[N_EDGES];               // per-edge rank within its dst
__device__ uint32_t g_xf[(size_t)MB * KB * 128];   // A frag plane (fp16x2)
__device__ uint32_t g_wf[64 * KB * 64];            // B frag plane (fp16x2)
__device__ __half   g_xw16[(size_t)MROWS * OUT_C];
__device__ int      g_sidx[N_EDGES];

// ---------------- helpers ----------------
__device__ __forceinline__ uint32_t pack_f16(float f0, float f1) {
    __half2 h = __floats2half2_rn(f0, f1);
    return *(uint32_t*)&h;
}

__device__ __forceinline__ void mma_f16(float* c, const uint32_t* a, const uint32_t* b) {
    asm volatile(
        "mma.sync.aligned.m16n8k16.row.col.f32.f16.f16.f32 "
        "{%0,%1,%2,%3}, {%4,%5,%6,%7}, {%8,%9}, {%0,%1,%2,%3};"
        : "+f"(c[0]), "+f"(c[1]), "+f"(c[2]), "+f"(c[3])
        : "r"(a[0]), "r"(a[1]), "r"(a[2]), "r"(a[3]), "r"(b[0]), "r"(b[1]));
}

__device__ __forceinline__ void load_edge(const void* ei, int e, int& s, int& d) {
    if (g_is64) {
        const long long* p = (const long long*)ei;
        s = (int)p[e];
        d = (int)p[N_EDGES + e];
    } else {
        const int* p = (const int*)ei;
        s = p[e];
        d = p[N_EDGES + e];
    }
}

// ---------------- preprocessing ----------------
__global__ __launch_bounds__(256) void k_init(const int* __restrict__ ei32) {
    int i = blockIdx.x * blockDim.x + threadIdx.x;
    const uint4 z = make_uint4(0, 0, 0, 0);
    if (i < 5000) ((uint4*)g_row_deg)[i] = z;
    else if (i < 6000) ((uint4*)g_col_deg)[i - 5000] = z;
    if (i == 0) g_nactive = 0;
    if (blockIdx.x == 0) {
        __shared__ int any_nonzero;
        if (threadIdx.x == 0) any_nonzero = 0;
        __syncthreads();
        for (int j = threadIdx.x * 2 + 1; j < 8192; j += blockDim.x * 2)
            if (ei32[j] != 0) any_nonzero = 1;
        __syncthreads();
        if (threadIdx.x == 0) g_is64 = any_nonzero ? 0 : 1;
    }
}

// fused: degree+rank (blocks 0..EBLK-1) + split_w (blocks EBLK..EBLK+511)
__global__ __launch_bounds__(256) void k_degree_splitw(const void* __restrict__ ei,
                                                       const float* __restrict__ W) {
    int b = blockIdx.x;
    if (b < EBLK) {
        int e = b * 256 + threadIdx.x;
        int s, d;
        load_edge(ei, e, s, d);
        if (s >= 0 && s < N_GENES) atomicAdd(&g_row_deg[s], 1);
        if (d >= 0 && d < N_DRUGS) g_rank[e] = atomicAdd(&g_col_deg[d], 1);
    } else {
        int id = (b - EBLK) * 256 + threadIdx.x;
        int lane = id & 31;
        int kb = (id >> 5) & 63;
        int nb = id >> 11;
        int n = nb * 8 + (lane >> 2);
        int kw = kb * 8 + (lane & 3);
        float fa0 = W[(size_t)(2 * kw) * OUT_C + n];
        float fa1 = W[(size_t)(2 * kw + 1) * OUT_C + n];
        float fb0 = W[(size_t)(2 * kw + 8) * OUT_C + n];
        float fb1 = W[(size_t)(2 * kw + 9) * OUT_C + n];
        uint2 h;
        h.x = pack_f16(fa0, fa1);
        h.y = pack_f16(fb0, fb1);
        size_t o = (size_t)(nb * KB + kb) * 32 + lane;
        ((uint2*)g_wf)[o] = h;
    }
}

// compact (blocks 0..19) + warp-shuffle exclusive scan (block 20)
__global__ void k_compact_scan() {
    if (blockIdx.x < 20) {
        int g = blockIdx.x * 1024 + threadIdx.x;
        if (g >= N_GENES) return;
        int deg = g_row_deg[g];
        if (deg > 0) {
            int idx = atomicAdd(&g_nactive, 1);
            g_active[idx] = g;
            g_rowmap[g] = idx;
            g_rowscale[idx] = rsqrtf((float)deg);
        }
    } else {
        __shared__ int warp_excl[32];
        int t = threadIdx.x;
        int lane = t & 31;
        int wid = t >> 5;
        int base = t * 4;
        int v[4];
        int s = 0;
#pragma unroll
        for (int i = 0; i < 4; i++) {
            v[i] = (base + i < N_DRUGS) ? g_col_deg[base + i] : 0;
            s += v[i];
        }
        int inc = s;
#pragma unroll
        for (int d = 1; d < 32; d <<= 1) {
            int x = __shfl_up_sync(0xffffffffu, inc, d);
            if (lane >= d) inc += x;
        }
        if (lane == 31) warp_excl[wid] = inc;
        __syncthreads();
        if (wid == 0) {
            int w = warp_excl[lane];
            int wi = w;
#pragma unroll
            for (int d = 1; d < 32; d <<= 1) {
                int x = __shfl_up_sync(0xffffffffu, wi, d);
                if (lane >= d) wi += x;
            }
            warp_excl[lane] = wi - w;
        }
        __syncthreads();
        int run = (inc - s) + warp_excl[wid];
#pragma unroll
        for (int i = 0; i < 4; i++) {
            if (base + i < N_DRUGS) {
                g_offs[base + i] = run;
                run += v[i];
            }
        }
    }
}

// place: atomic-free scatter using precomputed ranks
__global__ __launch_bounds__(256) void k_place(const void* __restrict__ ei) {
    int e = blockIdx.x * blockDim.x + threadIdx.x;
    if (e >= N_EDGES) return;
    int s, d;
    load_edge(ei, e, s, d);
    if (s < 0 || s >= N_GENES || d < 0 || d >= N_DRUGS) return;
    g_sidx[g_offs[d] + g_rank[e]] = g_rowmap[s];
}

// X active rows -> A frag plane. Two blocks per mb; loads batched for MLP.
__global__ __launch_bounds__(256) void k_split_x(const float* __restrict__ X) {
    const int mb = blockIdx.x >> 1;
    const int half = blockIdx.x & 1;
    const int m0 = mb * 16;
    const int nact = g_nactive;
    if (m0 >= nact) return;
    const int t = threadIdx.x;
    const int lane = t & 31;
    const int w = t >> 5;
    const int g = lane >> 2;
    const int kl = lane & 3;
    const int r0 = m0 + g;
    const int r1 = r0 + 8;
    const float* p0 = (r0 < nact) ? X + (size_t)g_active[r0] * IN_C : 0;
    const float* p1 = (r1 < nact) ? X + (size_t)g_active[r1] * IN_C : 0;
    const float2 z2 = make_float2(0.f, 0.f);

    float2 x0a[4], x0b[4], x1a[4], x1b[4];
#pragma unroll
    for (int i = 0; i < 4; i++) {
        int kb = half * 32 + i * 8 + w;
        int kwA = kb * 8 + kl;
        x0a[i] = p0 ? *(const float2*)(p0 + 2 * kwA) : z2;
        x0b[i] = p0 ? *(const float2*)(p0 + 2 * kwA + 8) : z2;
        x1a[i] = p1 ? *(const float2*)(p1 + 2 * kwA) : z2;
        x1b[i] = p1 ? *(const float2*)(p1 + 2 * kwA + 8) : z2;
    }
#pragma unroll
    for (int i = 0; i < 4; i++) {
        int kb = half * 32 + i * 8 + w;
        uint4 h;
        h.x = pack_f16(x0a[i].x, x0a[i].y);
        h.y = pack_f16(x1a[i].x, x1a[i].y);
        h.z = pack_f16(x0b[i].x, x0b[i].y);
        h.w = pack_f16(x1b[i].x, x1b[i].y);
        size_t o = (size_t)(mb * KB + kb) * 32 + lane;
        ((uint4*)g_xf)[o] = h;
    }
}

// ---------------- zero-staging fp16 GEMM, 4-slot pipeline (PF dist 3) ----------------
__global__ __launch_bounds__(256) void k_gemm(void) {
    const int nact = g_nactive;
    const int m0 = blockIdx.y * 128;
    if (m0 >= nact) return;
    const int n0 = blockIdx.x * 128;

    const int tid = threadIdx.x;
    const int wid = tid >> 5;
    const int lane = tid & 31;
    const int g = lane >> 2;
    const int tig = lane & 3;
    const int mwarp = (wid & 1) * 64;
    const int nwarp = (wid >> 1) * 32;
    const int mb0 = (m0 + mwarp) >> 4;
    const int nb0 = (n0 + nwarp) >> 3;

    const uint4* Af = (const uint4*)g_xf;
    const uint2* Bf = (const uint2*)g_wf;

    float acc[4][4][4];
#pragma unroll
    for (int i = 0; i < 4; i++)
#pragma unroll
        for (int j = 0; j < 4; j++)
#pragma unroll
            for (int r = 0; r < 4; r++) acc[i][j][r] = 0.f;

    uint4 ah[4][4];
    uint2 bh[4][4];

#define LOADK(buf, kb)                                                      \
    do {                                                                    \
        _Pragma("unroll")                                                   \
        for (int mf = 0; mf < 4; mf++) {                                    \
            size_t ai = (size_t)((mb0 + mf) * KB + (kb)) * 32 + lane;       \
            ah[buf][mf] = Af[ai];                                           \
        }                                                                   \
        _Pragma("unroll")                                                   \
        for (int nf = 0; nf < 4; nf++) {                                    \
            size_t bi = (size_t)((nb0 + nf) * KB + (kb)) * 32 + lane;       \
            bh[buf][nf] = Bf[bi];                                           \
        }                                                                   \
    } while (0)

    LOADK(0, 0);
    LOADK(1, 1);
    LOADK(2, 2);
#pragma unroll 4
    for (int kb = 0; kb < KB; kb++) {
        const int cur = kb & 3;
        if (kb + 3 < KB) LOADK((kb + 3) & 3, kb + 3);
#pragma unroll
        for (int mf = 0; mf < 4; mf++) {
#pragma unroll
            for (int nf = 0; nf < 4; nf++) {
                mma_f16(acc[mf][nf], (const uint32_t*)&ah[cur][mf],
                        (const uint32_t*)&bh[cur][nf]);
            }
        }
    }
#undef LOADK

    // epilogue: row scale, fp16 store
#pragma unroll
    for (int mf = 0; mf < 4; mf++) {
        int r0 = m0 + mwarp + mf * 16 + g;
        int r1 = r0 + 8;
#pragma unroll
        for (int nf = 0; nf < 4; nf++) {
            int col = n0 + nwarp + nf * 8 + tig * 2;
            if (r0 < nact) {
                float s0 = g_rowscale[r0];
                __half2 h = __float22half2_rn(
                    make_float2(acc[mf][nf][0] * s0, acc[mf][nf][1] * s0));
                *(__half2*)&g_xw16[(size_t)r0 * OUT_C + col] = h;
            }
            if (r1 < nact) {
                float s1 = g_rowscale[r1];
                __half2 h = __float22half2_rn(
                    make_float2(acc[mf][nf][2] * s1, acc[mf][nf][3] * s1));
                *(__half2*)&g_xw16[(size_t)r1 * OUT_C + col] = h;
            }
        }
    }
}

// ---------------- aggregation (fp16 gather, fp32 accumulate) ----------------
__device__ __forceinline__ void addv(float* acc, uint4 v) {
    const __half2* h = (const __half2*)&v;
#pragma unroll
    for (int j = 0; j < 4; j++) {
        float2 f = __half22float2(h[j]);
        acc[2 * j] += f.x;
        acc[2 * j + 1] += f.y;
    }
}

__global__ __launch_bounds__(64) void k_aggregate(const float* __restrict__ bias,
                                                  float* __restrict__ out) {
    int d = blockIdx.x;
    int t = threadIdx.x;
    int beg = g_offs[d];
    int n = g_col_deg[d];
    int end = beg + n;
    const uint4* xw = (const uint4*)g_xw16;

    float acc[8] = {0.f, 0.f, 0.f, 0.f, 0.f, 0.f, 0.f, 0.f};
    int i = beg;
    for (; i + 3 < end; i += 4) {
        int s0 = g_sidx[i], s1 = g_sidx[i + 1], s2 = g_sidx[i + 2], s3 = g_sidx[i + 3];
        uint4 v0 = xw[(size_t)s0 * 64 + t];
        uint4 v1 = xw[(size_t)s1 * 64 + t];
        uint4 v2 = xw[(size_t)s2 * 64 + t];
        uint4 v3 = xw[(size_t)s3 * 64 + t];
        addv(acc, v0);
        addv(acc, v1);
        addv(acc, v2);
        addv(acc, v3);
    }
    for (; i < end; i++) {
        uint4 v0 = xw[(size_t)g_sidx[i] * 64 + t];
        addv(acc, v0);
    }
    float cs = (n > 0) ? rsqrtf((float)n) : 0.f;
    float4 b0 = ((const float4*)bias)[t * 2];
    float4 b1 = ((const float4*)bias)[t * 2 + 1];
    float4 o0 = make_float4(acc[0] * cs + b0.x, acc[1] * cs + b0.y,
                            acc[2] * cs + b0.z, acc[3] * cs + b0.w);
    float4 o1 = make_float4(acc[4] * cs + b1.x, acc[5] * cs + b1.y,
                            acc[6] * cs + b1.z, acc[7] * cs + b1.w);
    ((float4*)out)[(size_t)d * 128 + t * 2] = o0;
    ((float4*)out)[(size_t)d * 128 + t * 2 + 1] = o1;
}

// ---------------- launch: minimal fork (place overlaps split_x + gemm) ----------------
extern "C" void kernel_launch(void* const* d_in, const int* in_sizes, int n_in,
                              void* d_out, int out_size) {
    const float* x = (const float*)d_in[0];
    const float* w = (const float*)d_in[1];
    const float* bias = (const float*)d_in[2];
    const void* ei = d_in[3];
    float* out = (float*)d_out;

    static cudaStream_t s2 = 0;
    static cudaEvent_t eC, eP;
    if (!s2) {
        cudaStreamCreateWithFlags(&s2, cudaStreamNonBlocking);
        cudaEventCreateWithFlags(&eC, cudaEventDisableTiming);
        cudaEventCreateWithFlags(&eP, cudaEventDisableTiming);
    }

    k_init<<<24, 256>>>((const int*)ei);
    k_degree_splitw<<<EBLK + 512, 256>>>(ei, w);
    k_compact_scan<<<21, 1024>>>();

    // fork: place runs on s2, overlapping split_x + gemm on stream 0
    cudaEventRecord(eC, 0);
    cudaStreamWaitEvent(s2, eC, 0);
    k_place<<<EBLK, 256, 0, s2>>>(ei);
    cudaEventRecord(eP, s2);

    k_split_x<<<MB * 2, 256>>>(x);
    dim3 gemm_grid(OUT_C / 128, MROWS / 128);
    k_gemm<<<gemm_grid, 256>>>();

    // join before aggregate
    cudaStreamWaitEvent(0, eP, 0);
    k_aggregate<<<N_DRUGS, 64>>>(bias, out);
}

// round 17
// speedup vs baseline: 1.1449x; 1.0096x over previous
#include <cuda_runtime.h>
#include <cuda_fp16.h>
#include <stdint.h>

// Problem constants
#define N_GENES 20000
#define N_DRUGS 4000
#define IN_C    1024
#define OUT_C   512
#define N_EDGES 262144
#define MROWS   20096          // padded rows (157 * 128)
#define MB      (MROWS / 16)   // 1256 A row-blocks
#define KB      64             // k16 blocks (1024/16)
#define EBLK    (N_EDGES / 256)

// ---------------- device scratch ----------------
__device__ int      g_row_deg[N_GENES];
__device__ int      g_col_deg[N_DRUGS];
__device__ int      g_offs[N_DRUGS];
__device__ int      g_active[N_GENES];
__device__ int      g_rowmap[N_GENES];
__device__ float    g_rowscale[N_GENES];
__device__ int      g_nactive;
__device__ int      g_is64;
__device__ int      g_rank[N_EDGES];               // per-edge rank within its dst
__device__ uint32_t g_xf[(size_t)MB * KB * 128];   // A frag plane (fp16x2)
__device__ uint32_t g_wf[64 * KB * 64];            // B frag plane (fp16x2)
__device__ __half   g_xw16[(size_t)MROWS * OUT_C];
__device__ int      g_sidx[N_EDGES];

// ---------------- helpers ----------------
__device__ __forceinline__ uint32_t pack_f16(float f0, float f1) {
    __half2 h = __floats2half2_rn(f0, f1);
    return *(uint32_t*)&h;
}

__device__ __forceinline__ void mma_f16(float* c, const uint32_t* a, const uint32_t* b) {
    asm volatile(
        "mma.sync.aligned.m16n8k16.row.col.f32.f16.f16.f32 "
        "{%0,%1,%2,%3}, {%4,%5,%6,%7}, {%8,%9}, {%0,%1,%2,%3};"
        : "+f"(c[0]), "+f"(c[1]), "+f"(c[2]), "+f"(c[3])
        : "r"(a[0]), "r"(a[1]), "r"(a[2]), "r"(a[3]), "r"(b[0]), "r"(b[1]));
}

__device__ __forceinline__ void load_edge(const void* ei, int e, int& s, int& d) {
    if (g_is64) {
        const long long* p = (const long long*)ei;
        s = (int)p[e];
        d = (int)p[N_EDGES + e];
    } else {
        const int* p = (const int*)ei;
        s = p[e];
        d = p[N_EDGES + e];
    }
}

// ---------------- preprocessing ----------------
__global__ __launch_bounds__(256) void k_init(const int* __restrict__ ei32) {
    int i = blockIdx.x * blockDim.x + threadIdx.x;
    const uint4 z = make_uint4(0, 0, 0, 0);
    if (i < 5000) ((uint4*)g_row_deg)[i] = z;
    else if (i < 6000) ((uint4*)g_col_deg)[i - 5000] = z;
    if (i == 0) g_nactive = 0;
    if (blockIdx.x == 0) {
        __shared__ int any_nonzero;
        if (threadIdx.x == 0) any_nonzero = 0;
        __syncthreads();
        for (int j = threadIdx.x * 2 + 1; j < 8192; j += blockDim.x * 2)
            if (ei32[j] != 0) any_nonzero = 1;
        __syncthreads();
        if (threadIdx.x == 0) g_is64 = any_nonzero ? 0 : 1;
    }
}

// fused: degree+rank (blocks 0..EBLK-1) + split_w (blocks EBLK..EBLK+511)
__global__ __launch_bounds__(256) void k_degree_splitw(const void* __restrict__ ei,
                                                       const float* __restrict__ W) {
    int b = blockIdx.x;
    if (b < EBLK) {
        int e = b * 256 + threadIdx.x;
        cudaGridDependencySynchronize();
        int s, d;
        load_edge(ei, e, s, d);
        if (s >= 0 && s < N_GENES) atomicAdd(&g_row_deg[s], 1);
        if (d >= 0 && d < N_DRUGS) g_rank[e] = atomicAdd(&g_col_deg[d], 1);
    } else {
        int id = (b - EBLK) * 256 + threadIdx.x;
        int lane = id & 31;
        int kb = (id >> 5) & 63;
        int nb = id >> 11;
        int n = nb * 8 + (lane >> 2);
        int kw = kb * 8 + (lane & 3);
        cudaGridDependencySynchronize();  // W is input; sync keeps chain semantics
        float fa0 = W[(size_t)(2 * kw) * OUT_C + n];
        float fa1 = W[(size_t)(2 * kw + 1) * OUT_C + n];
        float fb0 = W[(size_t)(2 * kw + 8) * OUT_C + n];
        float fb1 = W[(size_t)(2 * kw + 9) * OUT_C + n];
        uint2 h;
        h.x = pack_f16(fa0, fa1);
        h.y = pack_f16(fb0, fb1);
        size_t o = (size_t)(nb * KB + kb) * 32 + lane;
        ((uint2*)g_wf)[o] = h;
    }
}

// compact (blocks 0..19) + warp-shuffle exclusive scan (block 20)
__global__ void k_compact_scan() {
    cudaGridDependencySynchronize();
    if (blockIdx.x < 20) {
        int g = blockIdx.x * 1024 + threadIdx.x;
        if (g >= N_GENES) return;
        int deg = g_row_deg[g];
        if (deg > 0) {
            int idx = atomicAdd(&g_nactive, 1);
            g_active[idx] = g;
            g_rowmap[g] = idx;
            g_rowscale[idx] = rsqrtf((float)deg);
        }
    } else {
        __shared__ int warp_excl[32];
        int t = threadIdx.x;
        int lane = t & 31;
        int wid = t >> 5;
        int base = t * 4;
        int v[4];
        int s = 0;
#pragma unroll
        for (int i = 0; i < 4; i++) {
            v[i] = (base + i < N_DRUGS) ? g_col_deg[base + i] : 0;
            s += v[i];
        }
        int inc = s;
#pragma unroll
        for (int d = 1; d < 32; d <<= 1) {
            int x = __shfl_up_sync(0xffffffffu, inc, d);
            if (lane >= d) inc += x;
        }
        if (lane == 31) warp_excl[wid] = inc;
        __syncthreads();
        if (wid == 0) {
            int w = warp_excl[lane];
            int wi = w;
#pragma unroll
            for (int d = 1; d < 32; d <<= 1) {
                int x = __shfl_up_sync(0xffffffffu, wi, d);
                if (lane >= d) wi += x;
            }
            warp_excl[lane] = wi - w;
        }
        __syncthreads();
        int run = (inc - s) + warp_excl[wid];
#pragma unroll
        for (int i = 0; i < 4; i++) {
            if (base + i < N_DRUGS) {
                g_offs[base + i] = run;
                run += v[i];
            }
        }
    }
}

// place: atomic-free scatter using precomputed ranks (forked stream, event-ordered)
__global__ __launch_bounds__(256) void k_place(const void* __restrict__ ei) {
    int e = blockIdx.x * blockDim.x + threadIdx.x;
    if (e >= N_EDGES) return;
    int s, d;
    load_edge(ei, e, s, d);
    if (s < 0 || s >= N_GENES || d < 0 || d >= N_DRUGS) return;
    g_sidx[g_offs[d] + g_rank[e]] = g_rowmap[s];
}

// X active rows -> A frag plane. Two blocks per mb; loads batched for MLP.
__global__ __launch_bounds__(256) void k_split_x(const float* __restrict__ X) {
    const int mb = blockIdx.x >> 1;
    const int half = blockIdx.x & 1;
    const int m0 = mb * 16;
    const int t = threadIdx.x;
    const int lane = t & 31;
    const int w = t >> 5;
    const int g = lane >> 2;
    const int kl = lane & 3;
    cudaGridDependencySynchronize();
    const int nact = g_nactive;
    if (m0 >= nact) return;
    const int r0 = m0 + g;
    const int r1 = r0 + 8;
    const float* p0 = (r0 < nact) ? X + (size_t)g_active[r0] * IN_C : 0;
    const float* p1 = (r1 < nact) ? X + (size_t)g_active[r1] * IN_C : 0;
    const float2 z2 = make_float2(0.f, 0.f);

    float2 x0a[4], x0b[4], x1a[4], x1b[4];
#pragma unroll
    for (int i = 0; i < 4; i++) {
        int kb = half * 32 + i * 8 + w;
        int kwA = kb * 8 + kl;
        x0a[i] = p0 ? *(const float2*)(p0 + 2 * kwA) : z2;
        x0b[i] = p0 ? *(const float2*)(p0 + 2 * kwA + 8) : z2;
        x1a[i] = p1 ? *(const float2*)(p1 + 2 * kwA) : z2;
        x1b[i] = p1 ? *(const float2*)(p1 + 2 * kwA + 8) : z2;
    }
#pragma unroll
    for (int i = 0; i < 4; i++) {
        int kb = half * 32 + i * 8 + w;
        uint4 h;
        h.x = pack_f16(x0a[i].x, x0a[i].y);
        h.y = pack_f16(x1a[i].x, x1a[i].y);
        h.z = pack_f16(x0b[i].x, x0b[i].y);
        h.w = pack_f16(x1b[i].x, x1b[i].y);
        size_t o = (size_t)(mb * KB + kb) * 32 + lane;
        ((uint4*)g_xf)[o] = h;
    }
}

// ---------------- zero-staging fp16 GEMM, 4-slot pipeline (PF dist 3) ----------------
__global__ __launch_bounds__(256) void k_gemm(void) {
    const int tid = threadIdx.x;
    const int wid = tid >> 5;
    const int lane = tid & 31;
    const int g = lane >> 2;
    const int tig = lane & 3;
    const int mwarp = (wid & 1) * 64;
    const int nwarp = (wid >> 1) * 32;
    const int m0 = blockIdx.y * 128;
    const int n0 = blockIdx.x * 128;
    const int mb0 = (m0 + mwarp) >> 4;
    const int nb0 = (n0 + nwarp) >> 3;

    cudaGridDependencySynchronize();
    const int nact = g_nactive;
    if (m0 >= nact) return;

    const uint4* Af = (const uint4*)g_xf;
    const uint2* Bf = (const uint2*)g_wf;

    float acc[4][4][4];
#pragma unroll
    for (int i = 0; i < 4; i++)
#pragma unroll
        for (int j = 0; j < 4; j++)
#pragma unroll
            for (int r = 0; r < 4; r++) acc[i][j][r] = 0.f;

    uint4 ah[4][4];
    uint2 bh[4][4];

#define LOADK(buf, kb)                                                      \
    do {                                                                    \
        _Pragma("unroll")                                                   \
        for (int mf = 0; mf < 4; mf++) {                                    \
            size_t ai = (size_t)((mb0 + mf) * KB + (kb)) * 32 + lane;       \
            ah[buf][mf] = Af[ai];                                           \
        }                                                                   \
        _Pragma("unroll")                                                   \
        for (int nf = 0; nf < 4; nf++) {                                    \
            size_t bi = (size_t)((nb0 + nf) * KB + (kb)) * 32 + lane;       \
            bh[buf][nf] = Bf[bi];                                           \
        }                                                                   \
    } while (0)

    LOADK(0, 0);
    LOADK(1, 1);
    LOADK(2, 2);
#pragma unroll 4
    for (int kb = 0; kb < KB; kb++) {
        const int cur = kb & 3;
        if (kb + 3 < KB) LOADK((kb + 3) & 3, kb + 3);
#pragma unroll
        for (int mf = 0; mf < 4; mf++) {
#pragma unroll
            for (int nf = 0; nf < 4; nf++) {
                mma_f16(acc[mf][nf], (const uint32_t*)&ah[cur][mf],
                        (const uint32_t*)&bh[cur][nf]);
            }
        }
    }
#undef LOADK

    // epilogue: row scale, fp16 store
#pragma unroll
    for (int mf = 0; mf < 4; mf++) {
        int r0 = m0 + mwarp + mf * 16 + g;
        int r1 = r0 + 8;
#pragma unroll
        for (int nf = 0; nf < 4; nf++) {
            int col = n0 + nwarp + nf * 8 + tig * 2;
            if (r0 < nact) {
                float s0 = g_rowscale[r0];
                __half2 h = __float22half2_rn(
                    make_float2(acc[mf][nf][0] * s0, acc[mf][nf][1] * s0));
                *(__half2*)&g_xw16[(size_t)r0 * OUT_C + col] = h;
            }
            if (r1 < nact) {
                float s1 = g_rowscale[r1];
                __half2 h = __float22half2_rn(
                    make_float2(acc[mf][nf][2] * s1, acc[mf][nf][3] * s1));
                *(__half2*)&g_xw16[(size_t)r1 * OUT_C + col] = h;
            }
        }
    }
}

// ---------------- aggregation (fp16 gather, fp32 accumulate) ----------------
__device__ __forceinline__ void addv(float* acc, uint4 v) {
    const __half2* h = (const __half2*)&v;
#pragma unroll
    for (int j = 0; j < 4; j++) {
        float2 f = __half22float2(h[j]);
        acc[2 * j] += f.x;
        acc[2 * j + 1] += f.y;
    }
}

__global__ __launch_bounds__(64) void k_aggregate(const float* __restrict__ bias,
                                                  float* __restrict__ out) {
    int d = blockIdx.x;
    int t = threadIdx.x;
    cudaGridDependencySynchronize();
    int beg = g_offs[d];
    int n = g_col_deg[d];
    int end = beg + n;
    const uint4* xw = (const uint4*)g_xw16;

    float acc[8] = {0.f, 0.f, 0.f, 0.f, 0.f, 0.f, 0.f, 0.f};
    int i = beg;
    for (; i + 3 < end; i += 4) {
        int s0 = g_sidx[i], s1 = g_sidx[i + 1], s2 = g_sidx[i + 2], s3 = g_sidx[i + 3];
        uint4 v0 = xw[(size_t)s0 * 64 + t];
        uint4 v1 = xw[(size_t)s1 * 64 + t];
        uint4 v2 = xw[(size_t)s2 * 64 + t];
        uint4 v3 = xw[(size_t)s3 * 64 + t];
        addv(acc, v0);
        addv(acc, v1);
        addv(acc, v2);
        addv(acc, v3);
    }
    for (; i < end; i++) {
        uint4 v0 = xw[(size_t)g_sidx[i] * 64 + t];
        addv(acc, v0);
    }
    float cs = (n > 0) ? rsqrtf((float)n) : 0.f;
    float4 b0 = ((const float4*)bias)[t * 2];
    float4 b1 = ((const float4*)bias)[t * 2 + 1];
    float4 o0 = make_float4(acc[0] * cs + b0.x, acc[1] * cs + b0.y,
                            acc[2] * cs + b0.z, acc[3] * cs + b0.w);
    float4 o1 = make_float4(acc[4] * cs + b1.x, acc[5] * cs + b1.y,
                            acc[6] * cs + b1.z, acc[7] * cs + b1.w);
    ((float4*)out)[(size_t)d * 128 + t * 2] = o0;
    ((float4*)out)[(size_t)d * 128 + t * 2 + 1] = o1;
}

// ---------------- launch: PDL chain on s0 + place fork on s2 ----------------
template <typename K, typename... Args>
static inline void launch_pdl(K kernel, dim3 grid, dim3 block, cudaStream_t st,
                              Args... args) {
    cudaLaunchConfig_t cfg = {};
    cfg.gridDim = grid;
    cfg.blockDim = block;
    cfg.stream = st;
    cudaLaunchAttribute at[1];
    at[0].id = cudaLaunchAttributeProgrammaticStreamSerialization;
    at[0].val.programmaticStreamSerializationAllowed = 1;
    cfg.attrs = at;
    cfg.numAttrs = 1;
    cudaLaunchKernelEx(&cfg, kernel, args...);
}

extern "C" void kernel_launch(void* const* d_in, const int* in_sizes, int n_in,
                              void* d_out, int out_size) {
    const float* x = (const float*)d_in[0];
    const float* w = (const float*)d_in[1];
    const float* bias = (const float*)d_in[2];
    const void* ei = d_in[3];
    float* out = (float*)d_out;

    static cudaStream_t s2 = 0;
    static cudaEvent_t eC, eP;
    if (!s2) {
        cudaStreamCreateWithFlags(&s2, cudaStreamNonBlocking);
        cudaEventCreateWithFlags(&eC, cudaEventDisableTiming);
        cudaEventCreateWithFlags(&eP, cudaEventDisableTiming);
    }

    k_init<<<24, 256>>>((const int*)ei);
    launch_pdl(k_degree_splitw, dim3(EBLK + 512), dim3(256), (cudaStream_t)0, ei, w);
    launch_pdl(k_compact_scan, dim3(21), dim3(1024), (cudaStream_t)0);

    // fork: place runs on s2, overlapping split_x + gemm on stream 0
    cudaEventRecord(eC, 0);
    cudaStreamWaitEvent(s2, eC, 0);
    k_place<<<EBLK, 256, 0, s2>>>(ei);
    cudaEventRecord(eP, s2);

    launch_pdl(k_split_x, dim3(MB * 2), dim3(256), (cudaStream_t)0, x);
    launch_pdl(k_gemm, dim3(OUT_C / 128, MROWS / 128), dim3(256), (cudaStream_t)0);

    // join before aggregate
    cudaStreamWaitEvent(0, eP, 0);
    launch_pdl(k_aggregate, dim3(N_DRUGS), dim3(64), (cudaStream_t)0, bias, out);
}